// round 4
// baseline (speedup 1.0000x reference)
#include <cuda_runtime.h>
#include <cuda_bf16.h>

// Problem constants (FIXED by reference): N=20000, E=160000, NODE_DIM=64, EDGE_DIM=16, H=32, STEPS=3
#define NN     20000
#define EE     160000
#define HD     32
#define ND     64
#define ED     16
#define TSL    544          // 17 slices of 32: 16 edge-dims + 1 bias slice

// Scratch (allocation-free rule: __device__ globals)
__device__ int   g_flag;                     // 1 = float inputs are bf16, 0 = fp32
__device__ float g_h [NN * HD];              // node hidden state (fp32 internal)
__device__ float g_m [NN * HD];              // aggregated messages
__device__ float g_T [NN * TSL];             // per-node precomputed tensor (43.5 MB, L2-resident)
__device__ float g_W2[TSL * HD];             // reshaped edge weight

namespace {
struct EagerLoad {                            // materialize device globals at process start
    EagerLoad() { void* p = nullptr; (void)cudaGetSymbolAddress(&p, g_h); }
};
EagerLoad eager_load_;
}

// Dtype-agnostic float load (branch is warp-uniform on g_flag).
__device__ __forceinline__ float ldF(const void* p, long i, int bf) {
    return bf ? __bfloat162float(((const __nv_bfloat16*)p)[i])
              : ((const float*)p)[i];
}

// ---------------------------------------------------------------------------
// Detect input dtype from node_feat bit patterns.
// bf16 world: low 16 bits of each 32b word are a bf16 of ~N(0,1) -> its
// exponent field ((w>>7)&0xFF) lies in [110,140] ~99.9% of the time.
// fp32 world: those bits are uniform mantissa bits (~12% in band).
// ---------------------------------------------------------------------------
__global__ void detectKernel(const unsigned int* __restrict__ nf) {
    int lane = threadIdx.x;
    int cnt = 0;
    for (int i = lane; i < 1024; i += 32) {
        unsigned int e = (nf[i] >> 7) & 0xFF;
        cnt += (e >= 110 && e <= 140) ? 1 : 0;
    }
#pragma unroll
    for (int o = 16; o > 0; o >>= 1) cnt += __shfl_down_sync(0xffffffffu, cnt, o);
    if (lane == 0) g_flag = (cnt > 512) ? 1 : 0;
}

// ---------------------------------------------------------------------------
// Build W2: W2[(d*32+h)*32+k] = W_e[(h*32+k)*16+d]; slice d=16 holds b_e.
// ---------------------------------------------------------------------------
__global__ void buildW2Kernel(const void* __restrict__ We, const void* __restrict__ be) {
    int bf = g_flag;
    int i = blockIdx.x * 256 + threadIdx.x;
    if (i >= TSL * HD) return;
    int j = i >> 5, k = i & 31;                      // j = d*32 + h
    int d = j >> 5, h = j & 31;
    g_W2[i] = (d < 16) ? ldF(We, (h * 32 + k) * 16 + d, bf) : ldF(be, h * 32 + k, bf);
}

// ---------------------------------------------------------------------------
// h = node_feat @ W_np^T + b_np ; also zero g_m. Warp per node.
// ---------------------------------------------------------------------------
__global__ void nodeProjKernel(const void* __restrict__ nf, const void* __restrict__ W,
                               const void* __restrict__ b) {
    __shared__ float Ws[32 * 65];
    int bf = g_flag;
    int tid = threadIdx.x;
    for (int i = tid; i < 32 * 64; i += 256)
        Ws[(i >> 6) * 65 + (i & 63)] = ldF(W, i, bf);
    __syncthreads();

    g_m[blockIdx.x * 256 + tid] = 0.0f;              // exact cover: 2500*256 == N*H

    int n = blockIdx.x * 8 + (tid >> 5);
    int lane = tid & 31;

    float v0 = ldF(nf, n * 64 + lane, bf);
    float v1 = ldF(nf, n * 64 + 32 + lane, bf);
    float acc = ldF(b, lane, bf);
#pragma unroll
    for (int k = 0; k < 32; k++) {
        float a0 = __shfl_sync(0xffffffffu, v0, k);
        float a1 = __shfl_sync(0xffffffffu, v1, k);
        acc = fmaf(a0, Ws[lane * 65 + k], acc);
        acc = fmaf(a1, Ws[lane * 65 + 32 + k], acc);
    }
    g_h[n * 32 + lane] = acc;
}

// ---------------------------------------------------------------------------
// T[n, j] = sum_k W2[j][k] * h[n][k]  (all fp32 internal)
// ---------------------------------------------------------------------------
__global__ void compTKernel() {
    __shared__ __align__(16) float hs[64][32];
    int j = threadIdx.x;                              // 0..543
    int n0 = blockIdx.x * 64;

    float w[32];
#pragma unroll
    for (int k = 0; k < 32; k++) w[k] = g_W2[j * 32 + k];

    for (int i = j; i < 64 * 32; i += 544) {
        int n = n0 + (i >> 5);
        hs[i >> 5][i & 31] = (n < NN) ? g_h[n * 32 + (i & 31)] : 0.0f;
    }
    __syncthreads();

    int nend = NN - n0; if (nend > 64) nend = 64;
    for (int nl = 0; nl < nend; nl++) {
        const float4* h4 = reinterpret_cast<const float4*>(hs[nl]);
        float acc = 0.0f;
#pragma unroll
        for (int kk = 0; kk < 8; kk++) {
            float4 hv = h4[kk];
            acc = fmaf(hv.x, w[kk * 4 + 0], acc);
            acc = fmaf(hv.y, w[kk * 4 + 1], acc);
            acc = fmaf(hv.z, w[kk * 4 + 2], acc);
            acc = fmaf(hv.w, w[kk * 4 + 3], acc);
        }
        g_T[(size_t)(n0 + nl) * TSL + j] = acc;
    }
}

// ---------------------------------------------------------------------------
// msg[e,h] = T[src,512+h] + sum_d ef[e,d]*T[src,d*32+h]; atomicAdd into m[dst].
// ---------------------------------------------------------------------------
__global__ void msgKernel(const int* __restrict__ src, const int* __restrict__ dst,
                          const void* __restrict__ ef) {
    int bf = g_flag;
    int e = blockIdx.x * 8 + (threadIdx.x >> 5);     // grid exact: e < EE
    int lane = threadIdx.x & 31;

    int s = src[e]; if ((unsigned)s >= (unsigned)NN) s = 0;
    int d = dst[e]; if ((unsigned)d >= (unsigned)NN) d = 0;
    float efv = (lane < 16) ? ldF(ef, (long)e * 16 + lane, bf) : 0.0f;

    const float* Trow = g_T + (size_t)s * TSL;
    float acc = Trow[512 + lane];                    // bias slice
#pragma unroll
    for (int dd = 0; dd < 16; dd++) {
        float c = __shfl_sync(0xffffffffu, efv, dd);
        acc = fmaf(c, Trow[dd * 32 + lane], acc);
    }
    atomicAdd(&g_m[d * 32 + lane], acc);
}

// ---------------------------------------------------------------------------
// GRUCell (torch layout r,z,n). Warp per node. Final step writes d_out in the
// detected dtype; intermediate steps write fp32 g_h. Re-zeroes g_m.
// ---------------------------------------------------------------------------
__global__ void gruKernel(const void* __restrict__ W_ih, const void* __restrict__ W_hh,
                          const void* __restrict__ b_ih, const void* __restrict__ b_hh,
                          void* __restrict__ outp, int finalStep) {
    __shared__ float Wi[96 * 33];
    __shared__ float Wh[96 * 33];
    int bf = g_flag;
    int tid = threadIdx.x;
    for (int i = tid; i < 96 * 32; i += 256) {
        int j = i >> 5, k = i & 31;
        Wi[j * 33 + k] = ldF(W_ih, i, bf);
        Wh[j * 33 + k] = ldF(W_hh, i, bf);
    }
    __syncthreads();

    int n = blockIdx.x * 8 + (tid >> 5);             // grid exact: n < NN
    int lane = tid & 31;

    float mv = g_m[n * 32 + lane];
    float hv = g_h[n * 32 + lane];
    g_m[n * 32 + lane] = 0.0f;                       // reset for next step / replay

    float gi0 = ldF(b_ih, lane, bf), gi1 = ldF(b_ih, 32 + lane, bf), gi2 = ldF(b_ih, 64 + lane, bf);
    float gh0 = ldF(b_hh, lane, bf), gh1 = ldF(b_hh, 32 + lane, bf), gh2 = ldF(b_hh, 64 + lane, bf);
#pragma unroll
    for (int k = 0; k < 32; k++) {
        float mk = __shfl_sync(0xffffffffu, mv, k);
        float hk = __shfl_sync(0xffffffffu, hv, k);
        gi0 = fmaf(mk, Wi[lane * 33 + k],        gi0);
        gi1 = fmaf(mk, Wi[(32 + lane) * 33 + k], gi1);
        gi2 = fmaf(mk, Wi[(64 + lane) * 33 + k], gi2);
        gh0 = fmaf(hk, Wh[lane * 33 + k],        gh0);
        gh1 = fmaf(hk, Wh[(32 + lane) * 33 + k], gh1);
        gh2 = fmaf(hk, Wh[(64 + lane) * 33 + k], gh2);
    }
    float r  = 1.0f / (1.0f + __expf(-(gi0 + gh0)));
    float z  = 1.0f / (1.0f + __expf(-(gi1 + gh1)));
    float nn = tanhf(gi2 + r * gh2);
    float hnew = (1.0f - z) * nn + z * hv;

    if (finalStep) {
        if (bf) ((__nv_bfloat16*)outp)[n * 32 + lane] = __float2bfloat16(hnew);
        else    ((float*)outp)[n * 32 + lane] = hnew;
    } else {
        ((float*)outp)[n * 32 + lane] = hnew;        // g_h
    }
}

// ---------------------------------------------------------------------------
// Host: size-based binding (element counts) with positional fallback.
// ---------------------------------------------------------------------------
static int findBySz(const int* sizes, int n, long target, int occurrence) {
    int c = 0;
    for (int i = 0; i < n; i++)
        if ((long)sizes[i] == target) { if (c == occurrence) return i; c++; }
    return -1;
}

extern "C" void kernel_launch(void* const* d_in, const int* in_sizes, int n_in,
                              void* d_out, int out_size) {
    int i_nf = findBySz(in_sizes, n_in, (long)NN * ND, 0);
    int i_ei = findBySz(in_sizes, n_in, (long)2 * EE, 0);
    int i_ef = findBySz(in_sizes, n_in, (long)EE * ED, 0);
    int i_Wn = findBySz(in_sizes, n_in, (long)HD * ND, 0);
    int i_bn = findBySz(in_sizes, n_in, (long)HD, 0);
    int i_We = findBySz(in_sizes, n_in, (long)HD * HD * ED, 0);
    int i_be = findBySz(in_sizes, n_in, (long)HD * HD, 0);
    int i_g0 = findBySz(in_sizes, n_in, (long)3 * HD * HD, 0);
    int i_g1 = findBySz(in_sizes, n_in, (long)3 * HD * HD, 1);
    int i_q0 = findBySz(in_sizes, n_in, (long)3 * HD, 0);
    int i_q1 = findBySz(in_sizes, n_in, (long)3 * HD, 1);

    if (i_nf < 0 || i_ei < 0 || i_ef < 0 || i_Wn < 0 || i_bn < 0 ||
        i_We < 0 || i_be < 0 || i_g0 < 0 || i_g1 < 0 || i_q0 < 0 || i_q1 < 0) {
        i_nf = 0; i_ei = 1; i_ef = 2; i_Wn = 3; i_bn = 4;
        i_We = 5; i_be = 6; i_g0 = 7; i_g1 = 8; i_q0 = 9; i_q1 = 10;
    }

    const void* node_feat  = d_in[i_nf];
    const int*  edge_index = (const int*)d_in[i_ei];
    const void* edge_feat  = d_in[i_ef];
    const void* W_np       = d_in[i_Wn];
    const void* b_np       = d_in[i_bn];
    const void* W_e        = d_in[i_We];
    const void* b_e        = d_in[i_be];
    const void* W_ih       = d_in[i_g0];             // signature order: W_ih first
    const void* W_hh       = d_in[i_g1];
    const void* b_ih       = d_in[i_q0];
    const void* b_hh       = d_in[i_q1];

    const int* srcIdx = edge_index;                  // edge_index[0, :]
    const int* dstIdx = edge_index + EE;             // edge_index[1, :]

    detectKernel<<<1, 32>>>((const unsigned int*)node_feat);
    buildW2Kernel<<<(TSL * HD + 255) / 256, 256>>>(W_e, b_e);
    nodeProjKernel<<<NN / 8, 256>>>(node_feat, W_np, b_np);

    for (int step = 0; step < 3; step++) {
        compTKernel<<<(NN + 63) / 64, TSL>>>();
        msgKernel<<<EE / 8, 256>>>(srcIdx, dstIdx, edge_feat);
        int fin = (step == 2);
        void* hout = fin ? d_out : (void*)nullptr;   // g_h resolved device-side? no:
        // pass g_h address via symbol is not available host-side without API; use a
        // dedicated wrapper: obtain address once.
        static void* g_h_addr = nullptr;
        if (!g_h_addr) (void)cudaGetSymbolAddress(&g_h_addr, g_h);
        if (!fin) hout = g_h_addr;
        gruKernel<<<NN / 8, 256>>>(W_ih, W_hh, b_ih, b_hh, hout, fin);
    }
}

// round 5
// speedup vs baseline: 1.5852x; 1.5852x over previous
#include <cuda_runtime.h>
#include <cuda_bf16.h>

// Problem constants (FIXED by reference): N=20000, E=160000, NODE_DIM=64, EDGE_DIM=16, H=32, STEPS=3
#define NN     20000
#define EE     160000
#define HD     32
#define ND     64
#define ED     16
#define TSL    544          // 17 slices of 32: 16 edge-dims + 1 bias slice

// Scratch (allocation-free rule: __device__ globals)
__device__ int   g_flag;                     // 1 = float inputs are bf16, 0 = fp32
__device__ float g_h [NN * HD];              // node hidden state (fp32 internal)
__device__ float g_m [NN * HD];              // aggregated messages
__device__ float g_T [NN * TSL];             // per-node precomputed tensor (43.5 MB, L2-resident)
__device__ float g_W2[TSL * HD];             // reshaped edge weight

namespace {
struct EagerLoad {                            // materialize device globals at process start
    EagerLoad() { void* p = nullptr; (void)cudaGetSymbolAddress(&p, g_h); }
};
EagerLoad eager_load_;
}

// Dtype-agnostic float load (branch is warp-uniform on g_flag).
__device__ __forceinline__ float ldF(const void* p, long i, int bf) {
    return bf ? __bfloat162float(((const __nv_bfloat16*)p)[i])
              : ((const float*)p)[i];
}

// ---------------------------------------------------------------------------
// Detect input dtype from node_feat bit patterns (see R4 notes).
// ---------------------------------------------------------------------------
__global__ void detectKernel(const unsigned int* __restrict__ nf) {
    int lane = threadIdx.x;
    int cnt = 0;
    for (int i = lane; i < 1024; i += 32) {
        unsigned int e = (nf[i] >> 7) & 0xFF;
        cnt += (e >= 110 && e <= 140) ? 1 : 0;
    }
#pragma unroll
    for (int o = 16; o > 0; o >>= 1) cnt += __shfl_down_sync(0xffffffffu, cnt, o);
    if (lane == 0) g_flag = (cnt > 512) ? 1 : 0;
}

// ---------------------------------------------------------------------------
// Build W2: W2[(d*32+h)*32+k] = W_e[(h*32+k)*16+d]; slice d=16 holds b_e.
// ---------------------------------------------------------------------------
__global__ void buildW2Kernel(const void* __restrict__ We, const void* __restrict__ be) {
    int bf = g_flag;
    int i = blockIdx.x * 256 + threadIdx.x;
    if (i >= TSL * HD) return;
    int j = i >> 5, k = i & 31;                      // j = d*32 + h
    int d = j >> 5, h = j & 31;
    g_W2[i] = (d < 16) ? ldF(We, (h * 32 + k) * 16 + d, bf) : ldF(be, h * 32 + k, bf);
}

// ---------------------------------------------------------------------------
// h = node_feat @ W_np^T + b_np ; also zero g_m. Warp per node.
// ---------------------------------------------------------------------------
__global__ void nodeProjKernel(const void* __restrict__ nf, const void* __restrict__ W,
                               const void* __restrict__ b) {
    __shared__ float Ws[32 * 65];
    int bf = g_flag;
    int tid = threadIdx.x;
    for (int i = tid; i < 32 * 64; i += 256)
        Ws[(i >> 6) * 65 + (i & 63)] = ldF(W, i, bf);
    __syncthreads();

    g_m[blockIdx.x * 256 + tid] = 0.0f;              // exact cover: 2500*256 == N*H

    int n = blockIdx.x * 8 + (tid >> 5);
    int lane = tid & 31;

    float v0 = ldF(nf, n * 64 + lane, bf);
    float v1 = ldF(nf, n * 64 + 32 + lane, bf);
    float acc = ldF(b, lane, bf);
#pragma unroll
    for (int k = 0; k < 32; k++) {
        float a0 = __shfl_sync(0xffffffffu, v0, k);
        float a1 = __shfl_sync(0xffffffffu, v1, k);
        acc = fmaf(a0, Ws[lane * 65 + k], acc);
        acc = fmaf(a1, Ws[lane * 65 + 32 + k], acc);
    }
    g_h[n * 32 + lane] = acc;
}

// ---------------------------------------------------------------------------
// T[n, j] = sum_k W2[j][k] * h[n][k]
// 4-way node ILP: each thread carries 4 independent accumulator chains,
// killing the serial-FMA-latency bottleneck seen in R4 ncu (issue=35%).
// nend is always 64 or 32 -> divisible by 4, no tail.
// ---------------------------------------------------------------------------
__global__ void __launch_bounds__(TSL, 2) compTKernel() {
    __shared__ __align__(16) float hs[64][32];
    int j = threadIdx.x;                              // 0..543
    int n0 = blockIdx.x * 64;

    float w[32];
#pragma unroll
    for (int k = 0; k < 32; k++) w[k] = g_W2[j * 32 + k];

    for (int i = j; i < 64 * 32; i += 544) {
        int n = n0 + (i >> 5);
        hs[i >> 5][i & 31] = (n < NN) ? g_h[n * 32 + (i & 31)] : 0.0f;
    }
    __syncthreads();

    int nend = NN - n0; if (nend > 64) nend = 64;
    for (int nl = 0; nl < nend; nl += 4) {
        const float4* p0 = reinterpret_cast<const float4*>(hs[nl + 0]);
        const float4* p1 = reinterpret_cast<const float4*>(hs[nl + 1]);
        const float4* p2 = reinterpret_cast<const float4*>(hs[nl + 2]);
        const float4* p3 = reinterpret_cast<const float4*>(hs[nl + 3]);
        float a0 = 0.f, a1 = 0.f, a2 = 0.f, a3 = 0.f;
#pragma unroll
        for (int kk = 0; kk < 8; kk++) {
            float4 h0 = p0[kk], h1 = p1[kk], h2 = p2[kk], h3 = p3[kk];
            float w0 = w[kk * 4 + 0], w1 = w[kk * 4 + 1];
            float w2 = w[kk * 4 + 2], w3 = w[kk * 4 + 3];
            a0 = fmaf(h0.x, w0, a0); a1 = fmaf(h1.x, w0, a1);
            a2 = fmaf(h2.x, w0, a2); a3 = fmaf(h3.x, w0, a3);
            a0 = fmaf(h0.y, w1, a0); a1 = fmaf(h1.y, w1, a1);
            a2 = fmaf(h2.y, w1, a2); a3 = fmaf(h3.y, w1, a3);
            a0 = fmaf(h0.z, w2, a0); a1 = fmaf(h1.z, w2, a1);
            a2 = fmaf(h2.z, w2, a2); a3 = fmaf(h3.z, w2, a3);
            a0 = fmaf(h0.w, w3, a0); a1 = fmaf(h1.w, w3, a1);
            a2 = fmaf(h2.w, w3, a2); a3 = fmaf(h3.w, w3, a3);
        }
        size_t base = (size_t)(n0 + nl) * TSL + j;
        g_T[base          ] = a0;
        g_T[base + TSL    ] = a1;
        g_T[base + 2 * TSL] = a2;
        g_T[base + 3 * TSL] = a3;
    }
}

// ---------------------------------------------------------------------------
// msg[e,h] = T[src,512+h] + sum_d ef[e,d]*T[src,d*32+h]; atomicAdd into m[dst].
// T-row loads issued up-front (high MLP) before the FMA reduction.
// ---------------------------------------------------------------------------
__global__ void msgKernel(const int* __restrict__ src, const int* __restrict__ dst,
                          const void* __restrict__ ef) {
    int bf = g_flag;
    int e = blockIdx.x * 8 + (threadIdx.x >> 5);     // grid exact: e < EE
    int lane = threadIdx.x & 31;

    int s = src[e]; if ((unsigned)s >= (unsigned)NN) s = 0;
    int d = dst[e]; if ((unsigned)d >= (unsigned)NN) d = 0;
    float efv = (lane < 16) ? ldF(ef, (long)e * 16 + lane, bf) : 0.0f;

    const float* Trow = g_T + (size_t)s * TSL;
    float t[17];
#pragma unroll
    for (int dd = 0; dd < 16; dd++) t[dd] = Trow[dd * 32 + lane];    // batched loads
    t[16] = Trow[512 + lane];                                        // bias slice

    float acc = t[16];
#pragma unroll
    for (int dd = 0; dd < 16; dd++) {
        float c = __shfl_sync(0xffffffffu, efv, dd);
        acc = fmaf(c, t[dd], acc);
    }
    atomicAdd(&g_m[d * 32 + lane], acc);
}

// ---------------------------------------------------------------------------
// GRUCell (torch layout r,z,n). Warp per node; 6 independent FMA chains.
// Final step writes d_out in detected dtype. Re-zeroes g_m for replay.
// ---------------------------------------------------------------------------
__global__ void gruKernel(const void* __restrict__ W_ih, const void* __restrict__ W_hh,
                          const void* __restrict__ b_ih, const void* __restrict__ b_hh,
                          void* __restrict__ outp, int finalStep) {
    __shared__ float Wi[96 * 33];
    __shared__ float Wh[96 * 33];
    int bf = g_flag;
    int tid = threadIdx.x;
    for (int i = tid; i < 96 * 32; i += 256) {
        int j = i >> 5, k = i & 31;
        Wi[j * 33 + k] = ldF(W_ih, i, bf);
        Wh[j * 33 + k] = ldF(W_hh, i, bf);
    }
    __syncthreads();

    int n = blockIdx.x * 8 + (tid >> 5);             // grid exact: n < NN
    int lane = tid & 31;

    float mv = g_m[n * 32 + lane];
    float hv = g_h[n * 32 + lane];
    g_m[n * 32 + lane] = 0.0f;                       // reset for next step / replay

    float gi0 = ldF(b_ih, lane, bf), gi1 = ldF(b_ih, 32 + lane, bf), gi2 = ldF(b_ih, 64 + lane, bf);
    float gh0 = ldF(b_hh, lane, bf), gh1 = ldF(b_hh, 32 + lane, bf), gh2 = ldF(b_hh, 64 + lane, bf);
#pragma unroll
    for (int k = 0; k < 32; k++) {
        float mk = __shfl_sync(0xffffffffu, mv, k);
        float hk = __shfl_sync(0xffffffffu, hv, k);
        gi0 = fmaf(mk, Wi[lane * 33 + k],        gi0);
        gi1 = fmaf(mk, Wi[(32 + lane) * 33 + k], gi1);
        gi2 = fmaf(mk, Wi[(64 + lane) * 33 + k], gi2);
        gh0 = fmaf(hk, Wh[lane * 33 + k],        gh0);
        gh1 = fmaf(hk, Wh[(32 + lane) * 33 + k], gh1);
        gh2 = fmaf(hk, Wh[(64 + lane) * 33 + k], gh2);
    }
    float r  = 1.0f / (1.0f + __expf(-(gi0 + gh0)));
    float z  = 1.0f / (1.0f + __expf(-(gi1 + gh1)));
    float nn = tanhf(gi2 + r * gh2);
    float hnew = (1.0f - z) * nn + z * hv;

    if (finalStep) {
        if (bf) ((__nv_bfloat16*)outp)[n * 32 + lane] = __float2bfloat16(hnew);
        else    ((float*)outp)[n * 32 + lane] = hnew;
    } else {
        ((float*)outp)[n * 32 + lane] = hnew;        // g_h
    }
}

// ---------------------------------------------------------------------------
// Host: size-based binding (element counts) with positional fallback.
// ---------------------------------------------------------------------------
static int findBySz(const int* sizes, int n, long target, int occurrence) {
    int c = 0;
    for (int i = 0; i < n; i++)
        if ((long)sizes[i] == target) { if (c == occurrence) return i; c++; }
    return -1;
}

extern "C" void kernel_launch(void* const* d_in, const int* in_sizes, int n_in,
                              void* d_out, int out_size) {
    int i_nf = findBySz(in_sizes, n_in, (long)NN * ND, 0);
    int i_ei = findBySz(in_sizes, n_in, (long)2 * EE, 0);
    int i_ef = findBySz(in_sizes, n_in, (long)EE * ED, 0);
    int i_Wn = findBySz(in_sizes, n_in, (long)HD * ND, 0);
    int i_bn = findBySz(in_sizes, n_in, (long)HD, 0);
    int i_We = findBySz(in_sizes, n_in, (long)HD * HD * ED, 0);
    int i_be = findBySz(in_sizes, n_in, (long)HD * HD, 0);
    int i_g0 = findBySz(in_sizes, n_in, (long)3 * HD * HD, 0);
    int i_g1 = findBySz(in_sizes, n_in, (long)3 * HD * HD, 1);
    int i_q0 = findBySz(in_sizes, n_in, (long)3 * HD, 0);
    int i_q1 = findBySz(in_sizes, n_in, (long)3 * HD, 1);

    if (i_nf < 0 || i_ei < 0 || i_ef < 0 || i_Wn < 0 || i_bn < 0 ||
        i_We < 0 || i_be < 0 || i_g0 < 0 || i_g1 < 0 || i_q0 < 0 || i_q1 < 0) {
        i_nf = 0; i_ei = 1; i_ef = 2; i_Wn = 3; i_bn = 4;
        i_We = 5; i_be = 6; i_g0 = 7; i_g1 = 8; i_q0 = 9; i_q1 = 10;
    }

    const void* node_feat  = d_in[i_nf];
    const int*  edge_index = (const int*)d_in[i_ei];
    const void* edge_feat  = d_in[i_ef];
    const void* W_np       = d_in[i_Wn];
    const void* b_np       = d_in[i_bn];
    const void* W_e        = d_in[i_We];
    const void* b_e        = d_in[i_be];
    const void* W_ih       = d_in[i_g0];             // signature order: W_ih first
    const void* W_hh       = d_in[i_g1];
    const void* b_ih       = d_in[i_q0];
    const void* b_hh       = d_in[i_q1];

    const int* srcIdx = edge_index;                  // edge_index[0, :]
    const int* dstIdx = edge_index + EE;             // edge_index[1, :]

    static void* g_h_addr = nullptr;
    if (!g_h_addr) (void)cudaGetSymbolAddress(&g_h_addr, g_h);

    detectKernel<<<1, 32>>>((const unsigned int*)node_feat);
    buildW2Kernel<<<(TSL * HD + 255) / 256, 256>>>(W_e, b_e);
    nodeProjKernel<<<NN / 8, 256>>>(node_feat, W_np, b_np);

    for (int step = 0; step < 3; step++) {
        compTKernel<<<(NN + 63) / 64, TSL>>>();
        msgKernel<<<EE / 8, 256>>>(srcIdx, dstIdx, edge_feat);
        int fin = (step == 2);
        void* hout = fin ? d_out : g_h_addr;
        gruKernel<<<NN / 8, 256>>>(W_ih, W_hh, b_ih, b_hh, hout, fin);
    }
}

// round 6
// speedup vs baseline: 1.6575x; 1.0457x over previous
#include <cuda_runtime.h>
#include <cuda_bf16.h>

// Problem constants (FIXED by reference): N=20000, E=160000, NODE_DIM=64, EDGE_DIM=16, H=32, STEPS=3
#define NN     20000
#define EE     160000
#define HD     32
#define ND     64
#define ED     16
#define TSL    576          // padded row stride: 18 slices of 32 (16 edge-dims + bias + pad)
#define JUSED  544          // j slots actually consumed by msgKernel

// Scratch (allocation-free rule: __device__ globals)
__device__ int   g_flag;                     // 1 = float inputs are bf16, 0 = fp32
__device__ float g_h [NN * HD];              // node hidden state (fp32 internal)
__device__ float g_m [NN * HD];              // aggregated messages
__device__ float g_T [NN * TSL];             // per-node precomputed tensor (46 MB, L2-resident)
__device__ float g_W2[TSL * HD];             // reshaped edge weight (rows >= 544 are zero)

namespace {
struct EagerLoad {                            // materialize device globals at process start
    EagerLoad() { void* p = nullptr; (void)cudaGetSymbolAddress(&p, g_h); }
};
EagerLoad eager_load_;
}

// Dtype-agnostic float load (branch is warp-uniform on g_flag).
__device__ __forceinline__ float ldF(const void* p, long i, int bf) {
    return bf ? __bfloat162float(((const __nv_bfloat16*)p)[i])
              : ((const float*)p)[i];
}

// ---------------------------------------------------------------------------
// Detect input dtype from node_feat bit patterns (see R4 notes).
// ---------------------------------------------------------------------------
__global__ void detectKernel(const unsigned int* __restrict__ nf) {
    int lane = threadIdx.x;
    int cnt = 0;
    for (int i = lane; i < 1024; i += 32) {
        unsigned int e = (nf[i] >> 7) & 0xFF;
        cnt += (e >= 110 && e <= 140) ? 1 : 0;
    }
#pragma unroll
    for (int o = 16; o > 0; o >>= 1) cnt += __shfl_down_sync(0xffffffffu, cnt, o);
    if (lane == 0) g_flag = (cnt > 512) ? 1 : 0;
}

// ---------------------------------------------------------------------------
// Build W2: W2[(d*32+h)*32+k] = W_e[(h*32+k)*16+d]; slice d=16 holds b_e;
// slice d=17 (pad) is zero.
// ---------------------------------------------------------------------------
__global__ void buildW2Kernel(const void* __restrict__ We, const void* __restrict__ be) {
    int bf = g_flag;
    int i = blockIdx.x * 256 + threadIdx.x;
    if (i >= TSL * HD) return;
    int j = i >> 5, k = i & 31;                      // j = d*32 + h
    int d = j >> 5, h = j & 31;
    float v = 0.0f;
    if (d < 16)       v = ldF(We, (h * 32 + k) * 16 + d, bf);
    else if (d == 16) v = ldF(be, h * 32 + k, bf);
    g_W2[i] = v;
}

// ---------------------------------------------------------------------------
// h = node_feat @ W_np^T + b_np ; also zero g_m. Warp per node.
// ---------------------------------------------------------------------------
__global__ void nodeProjKernel(const void* __restrict__ nf, const void* __restrict__ W,
                               const void* __restrict__ b) {
    __shared__ float Ws[32 * 65];
    int bf = g_flag;
    int tid = threadIdx.x;
    for (int i = tid; i < 32 * 64; i += 256)
        Ws[(i >> 6) * 65 + (i & 63)] = ldF(W, i, bf);
    __syncthreads();

    g_m[blockIdx.x * 256 + tid] = 0.0f;              // exact cover: 2500*256 == N*H

    int n = blockIdx.x * 8 + (tid >> 5);
    int lane = tid & 31;

    float v0 = ldF(nf, n * 64 + lane, bf);
    float v1 = ldF(nf, n * 64 + 32 + lane, bf);
    float acc = ldF(b, lane, bf);
#pragma unroll
    for (int k = 0; k < 32; k++) {
        float a0 = __shfl_sync(0xffffffffu, v0, k);
        float a1 = __shfl_sync(0xffffffffu, v1, k);
        acc = fmaf(a0, Ws[lane * 65 + k], acc);
        acc = fmaf(a1, Ws[lane * 65 + 32 + k], acc);
    }
    g_h[n * 32 + lane] = acc;
}

// ---------------------------------------------------------------------------
// T[n, j] = sum_k W2[j][k] * h[n][k]
// 288 threads (9 warps), each owns TWO W2 rows (j, j+288) and FOUR nodes of
// ILP -> 8 FFMA per LDS.128 element group: shared-pipe load halved vs R5
// (which ncu showed L1=58.8% bound), FFMA becomes the limiter.
// ---------------------------------------------------------------------------
__global__ void __launch_bounds__(288, 2) compTKernel() {
    __shared__ __align__(16) float hs[64][32];
    int t = threadIdx.x;                              // 0..287
    int n0 = blockIdx.x * 64;

    float w0[32], w1[32];
#pragma unroll
    for (int k = 0; k < 32; k++) {
        w0[k] = g_W2[t * 32 + k];
        w1[k] = g_W2[(t + 288) * 32 + k];
    }

    for (int i = t; i < 64 * 32; i += 288) {
        int n = n0 + (i >> 5);
        hs[i >> 5][i & 31] = (n < NN) ? g_h[n * 32 + (i & 31)] : 0.0f;
    }
    __syncthreads();

    int nend = NN - n0; if (nend > 64) nend = 64;     // 64 or 32; divisible by 4
    for (int nl = 0; nl < nend; nl += 4) {
        const float4* p0 = reinterpret_cast<const float4*>(hs[nl + 0]);
        const float4* p1 = reinterpret_cast<const float4*>(hs[nl + 1]);
        const float4* p2 = reinterpret_cast<const float4*>(hs[nl + 2]);
        const float4* p3 = reinterpret_cast<const float4*>(hs[nl + 3]);
        float a0 = 0.f, a1 = 0.f, a2 = 0.f, a3 = 0.f;  // j = t
        float b0 = 0.f, b1 = 0.f, b2 = 0.f, b3 = 0.f;  // j = t + 288
#pragma unroll
        for (int kk = 0; kk < 8; kk++) {
            float4 h0 = p0[kk], h1 = p1[kk], h2 = p2[kk], h3 = p3[kk];
#pragma unroll
            for (int q = 0; q < 4; q++) {
                float hv0 = (&h0.x)[q], hv1 = (&h1.x)[q];
                float hv2 = (&h2.x)[q], hv3 = (&h3.x)[q];
                float wa = w0[kk * 4 + q], wb = w1[kk * 4 + q];
                a0 = fmaf(hv0, wa, a0); a1 = fmaf(hv1, wa, a1);
                a2 = fmaf(hv2, wa, a2); a3 = fmaf(hv3, wa, a3);
                b0 = fmaf(hv0, wb, b0); b1 = fmaf(hv1, wb, b1);
                b2 = fmaf(hv2, wb, b2); b3 = fmaf(hv3, wb, b3);
            }
        }
        size_t base = (size_t)(n0 + nl) * TSL + t;
        g_T[base          ] = a0;  g_T[base           + 288] = b0;
        g_T[base +     TSL] = a1;  g_T[base +     TSL + 288] = b1;
        g_T[base + 2 * TSL] = a2;  g_T[base + 2 * TSL + 288] = b2;
        g_T[base + 3 * TSL] = a3;  g_T[base + 3 * TSL + 288] = b3;
    }
}

// ---------------------------------------------------------------------------
// msg[e,h] = T[src,512+h] + sum_d ef[e,d]*T[src,d*32+h]; atomicAdd into m[dst].
// T-row loads issued up-front (high MLP) before the FMA reduction.
// ---------------------------------------------------------------------------
__global__ void msgKernel(const int* __restrict__ src, const int* __restrict__ dst,
                          const void* __restrict__ ef) {
    int bf = g_flag;
    int e = blockIdx.x * 8 + (threadIdx.x >> 5);     // grid exact: e < EE
    int lane = threadIdx.x & 31;

    int s = src[e]; if ((unsigned)s >= (unsigned)NN) s = 0;
    int d = dst[e]; if ((unsigned)d >= (unsigned)NN) d = 0;
    float efv = (lane < 16) ? ldF(ef, (long)e * 16 + lane, bf) : 0.0f;

    const float* Trow = g_T + (size_t)s * TSL;
    float t[17];
#pragma unroll
    for (int dd = 0; dd < 16; dd++) t[dd] = Trow[dd * 32 + lane];    // batched loads
    t[16] = Trow[512 + lane];                                        // bias slice

    float acc = t[16];
#pragma unroll
    for (int dd = 0; dd < 16; dd++) {
        float c = __shfl_sync(0xffffffffu, efv, dd);
        acc = fmaf(c, t[dd], acc);
    }
    atomicAdd(&g_m[d * 32 + lane], acc);
}

// ---------------------------------------------------------------------------
// GRUCell (torch layout r,z,n). Warp per node; 6 independent FMA chains.
// Final step writes d_out in detected dtype. Re-zeroes g_m for replay.
// ---------------------------------------------------------------------------
__global__ void gruKernel(const void* __restrict__ W_ih, const void* __restrict__ W_hh,
                          const void* __restrict__ b_ih, const void* __restrict__ b_hh,
                          void* __restrict__ outp, int finalStep) {
    __shared__ float Wi[96 * 33];
    __shared__ float Wh[96 * 33];
    int bf = g_flag;
    int tid = threadIdx.x;
    for (int i = tid; i < 96 * 32; i += 256) {
        int j = i >> 5, k = i & 31;
        Wi[j * 33 + k] = ldF(W_ih, i, bf);
        Wh[j * 33 + k] = ldF(W_hh, i, bf);
    }
    __syncthreads();

    int n = blockIdx.x * 8 + (tid >> 5);             // grid exact: n < NN
    int lane = tid & 31;

    float mv = g_m[n * 32 + lane];
    float hv = g_h[n * 32 + lane];
    g_m[n * 32 + lane] = 0.0f;                       // reset for next step / replay

    float gi0 = ldF(b_ih, lane, bf), gi1 = ldF(b_ih, 32 + lane, bf), gi2 = ldF(b_ih, 64 + lane, bf);
    float gh0 = ldF(b_hh, lane, bf), gh1 = ldF(b_hh, 32 + lane, bf), gh2 = ldF(b_hh, 64 + lane, bf);
#pragma unroll
    for (int k = 0; k < 32; k++) {
        float mk = __shfl_sync(0xffffffffu, mv, k);
        float hk = __shfl_sync(0xffffffffu, hv, k);
        gi0 = fmaf(mk, Wi[lane * 33 + k],        gi0);
        gi1 = fmaf(mk, Wi[(32 + lane) * 33 + k], gi1);
        gi2 = fmaf(mk, Wi[(64 + lane) * 33 + k], gi2);
        gh0 = fmaf(hk, Wh[lane * 33 + k],        gh0);
        gh1 = fmaf(hk, Wh[(32 + lane) * 33 + k], gh1);
        gh2 = fmaf(hk, Wh[(64 + lane) * 33 + k], gh2);
    }
    float r  = 1.0f / (1.0f + __expf(-(gi0 + gh0)));
    float z  = 1.0f / (1.0f + __expf(-(gi1 + gh1)));
    float nn = tanhf(gi2 + r * gh2);
    float hnew = (1.0f - z) * nn + z * hv;

    if (finalStep) {
        if (bf) ((__nv_bfloat16*)outp)[n * 32 + lane] = __float2bfloat16(hnew);
        else    ((float*)outp)[n * 32 + lane] = hnew;
    } else {
        ((float*)outp)[n * 32 + lane] = hnew;        // g_h
    }
}

// ---------------------------------------------------------------------------
// Host: size-based binding (element counts) with positional fallback.
// ---------------------------------------------------------------------------
static int findBySz(const int* sizes, int n, long target, int occurrence) {
    int c = 0;
    for (int i = 0; i < n; i++)
        if ((long)sizes[i] == target) { if (c == occurrence) return i; c++; }
    return -1;
}

extern "C" void kernel_launch(void* const* d_in, const int* in_sizes, int n_in,
                              void* d_out, int out_size) {
    int i_nf = findBySz(in_sizes, n_in, (long)NN * ND, 0);
    int i_ei = findBySz(in_sizes, n_in, (long)2 * EE, 0);
    int i_ef = findBySz(in_sizes, n_in, (long)EE * ED, 0);
    int i_Wn = findBySz(in_sizes, n_in, (long)HD * ND, 0);
    int i_bn = findBySz(in_sizes, n_in, (long)HD, 0);
    int i_We = findBySz(in_sizes, n_in, (long)HD * HD * ED, 0);
    int i_be = findBySz(in_sizes, n_in, (long)HD * HD, 0);
    int i_g0 = findBySz(in_sizes, n_in, (long)3 * HD * HD, 0);
    int i_g1 = findBySz(in_sizes, n_in, (long)3 * HD * HD, 1);
    int i_q0 = findBySz(in_sizes, n_in, (long)3 * HD, 0);
    int i_q1 = findBySz(in_sizes, n_in, (long)3 * HD, 1);

    if (i_nf < 0 || i_ei < 0 || i_ef < 0 || i_Wn < 0 || i_bn < 0 ||
        i_We < 0 || i_be < 0 || i_g0 < 0 || i_g1 < 0 || i_q0 < 0 || i_q1 < 0) {
        i_nf = 0; i_ei = 1; i_ef = 2; i_Wn = 3; i_bn = 4;
        i_We = 5; i_be = 6; i_g0 = 7; i_g1 = 8; i_q0 = 9; i_q1 = 10;
    }

    const void* node_feat  = d_in[i_nf];
    const int*  edge_index = (const int*)d_in[i_ei];
    const void* edge_feat  = d_in[i_ef];
    const void* W_np       = d_in[i_Wn];
    const void* b_np       = d_in[i_bn];
    const void* W_e        = d_in[i_We];
    const void* b_e        = d_in[i_be];
    const void* W_ih       = d_in[i_g0];             // signature order: W_ih first
    const void* W_hh       = d_in[i_g1];
    const void* b_ih       = d_in[i_q0];
    const void* b_hh       = d_in[i_q1];

    const int* srcIdx = edge_index;                  // edge_index[0, :]
    const int* dstIdx = edge_index + EE;             // edge_index[1, :]

    static void* g_h_addr = nullptr;
    if (!g_h_addr) (void)cudaGetSymbolAddress(&g_h_addr, g_h);

    detectKernel<<<1, 32>>>((const unsigned int*)node_feat);
    buildW2Kernel<<<(TSL * HD + 255) / 256, 256>>>(W_e, b_e);
    nodeProjKernel<<<NN / 8, 256>>>(node_feat, W_np, b_np);

    for (int step = 0; step < 3; step++) {
        compTKernel<<<(NN + 63) / 64, 288>>>();
        msgKernel<<<EE / 8, 256>>>(srcIdx, dstIdx, edge_feat);
        int fin = (step == 2);
        void* hout = fin ? d_out : g_h_addr;
        gruKernel<<<NN / 8, 256>>>(W_ih, W_hh, b_ih, b_hh, hout, fin);
    }
}